// round 6
// baseline (speedup 1.0000x reference)
#include <cuda_runtime.h>
#include <math.h>
#include <stdint.h>

// ---------------------------------------------------------------------------
// Problem constants
// ---------------------------------------------------------------------------
#define BATCH   8
#define RESO    64
#define LTOK    (RESO * RESO)        // 4096
#define CDIM    384
#define MLPH    (4 * CDIM)           // 1536
#define ROWS    (BATCH * LTOK)       // 32768
#define CB      (CDIM / 2)           // 192
#define NHB     6                    // heads per branch
#define HD      32
#define NWIN    256
#define WIN_PER_B 16
#define NWINDOWS (BATCH * WIN_PER_B) // 128

// ---------------------------------------------------------------------------
// Scratch (device globals; no allocation allowed)
// ---------------------------------------------------------------------------
__device__ float g_ln  [ROWS * CDIM];
__device__ float g_qkv [ROWS * 3 * CDIM];
__device__ float g_attn[ROWS * CDIM];
__device__ float g_x1  [ROWS * CDIM];
__device__ float g_mlp [ROWS * MLPH];
// tf32-rounded weight copies
__device__ float g_wq [3 * CDIM * CDIM];
__device__ float g_wp [CDIM * CDIM];
__device__ float g_w1 [MLPH * CDIM];
__device__ float g_w2 [CDIM * MLPH];

__device__ __forceinline__ float to_tf32(float x) {
    unsigned u;
    asm("cvt.rna.tf32.f32 %0, %1;" : "=r"(u) : "f"(x));
    return __uint_as_float(u);
}

// ---------------------------------------------------------------------------
// Round fp32 array to tf32 (weights)
// ---------------------------------------------------------------------------
__global__ void round_tf32_kernel(const float* __restrict__ in,
                                  float* __restrict__ outp, int n)
{
    int i = blockIdx.x * 256 + threadIdx.x;
    if (i < n) outp[i] = to_tf32(in[i]);
}

// ---------------------------------------------------------------------------
// LayerNorm (tf32-rounded output — always feeds a GEMM A operand)
// ---------------------------------------------------------------------------
__global__ __launch_bounds__(128) void ln_kernel(
    const float* __restrict__ x, const float* __restrict__ w,
    const float* __restrict__ b, float* __restrict__ out)
{
    int row = blockIdx.x;
    const float* xr = x + (size_t)row * CDIM;
    int t = threadIdx.x;

    float v0 = xr[t], v1 = xr[t + 128], v2 = xr[t + 256];
    float s  = v0 + v1 + v2;
    float ss = v0 * v0 + v1 * v1 + v2 * v2;

    #pragma unroll
    for (int o = 16; o > 0; o >>= 1) {
        s  += __shfl_down_sync(0xffffffffu, s,  o);
        ss += __shfl_down_sync(0xffffffffu, ss, o);
    }
    __shared__ float sh_s[4], sh_ss[4], sh_mu, sh_rstd;
    int wid = t >> 5, lane = t & 31;
    if (lane == 0) { sh_s[wid] = s; sh_ss[wid] = ss; }
    __syncthreads();
    if (t == 0) {
        float S  = sh_s[0] + sh_s[1] + sh_s[2] + sh_s[3];
        float SS = sh_ss[0] + sh_ss[1] + sh_ss[2] + sh_ss[3];
        float mu = S * (1.0f / CDIM);
        float var = SS * (1.0f / CDIM) - mu * mu;
        sh_mu = mu; sh_rstd = rsqrtf(var + 1e-5f);
    }
    __syncthreads();
    float mu = sh_mu, r = sh_rstd;
    float* orow = out + (size_t)row * CDIM;
    orow[t]       = to_tf32((v0 - mu) * r * w[t]       + b[t]);
    orow[t + 128] = to_tf32((v1 - mu) * r * w[t + 128] + b[t + 128]);
    orow[t + 256] = to_tf32((v2 - mu) * r * w[t + 256] + b[t + 256]);
}

// ---------------------------------------------------------------------------
// TF32 tensor-core GEMM v2: C[M,N] = A[M,K] @ W[N,K]^T + bias (+gelu) (+res)
// 128x128x32 block tile, 128 threads = 4 warps (2x2), 64x64 warp tile.
// Per kk-step: 32 LDS feed 32 mma (1.0 LDS/mma vs 1.5 in R3).
// cp.async double-buffered smem; PADK=36 conflict-free fragment reads.
// ---------------------------------------------------------------------------
#define PADK 36

__device__ __forceinline__ void cp16(uint32_t dst, const float* src) {
    asm volatile("cp.async.ca.shared.global [%0], [%1], 16;\n"
                 :: "r"(dst), "l"(src));
}

__global__ __launch_bounds__(128, 2) void gemm_tc_kernel(
    const float* __restrict__ A, const float* __restrict__ Wt,
    const float* __restrict__ bias, const float* __restrict__ res,
    float* __restrict__ Cout, int M, int N, int K,
    int act_gelu, int round_out)
{
    extern __shared__ float smem[];
    float* As[2] = { smem,               smem + 2 * 128 * PADK };
    float* Bs[2] = { smem + 128 * PADK,  smem + 3 * 128 * PADK };

    int n0 = blockIdx.x * 128;
    int m0 = blockIdx.y * 128;
    int t  = threadIdx.x;
    int w  = t >> 5;
    int lane = t & 31;
    int g   = lane >> 2;      // 0..7
    int tig = lane & 3;       // 0..3
    int wm  = w >> 1;         // 0..1 (M)
    int wn  = w & 1;          // 0..1 (N)

    float acc[4][8][4];
    #pragma unroll
    for (int i = 0; i < 4; i++)
        #pragma unroll
        for (int j = 0; j < 8; j++)
            #pragma unroll
            for (int r = 0; r < 4; r++) acc[i][j][r] = 0.0f;

    uint32_t sA[2], sB[2];
    {
        uint32_t base = (uint32_t)__cvta_generic_to_shared(smem);
        sA[0] = base;
        sB[0] = base + 128 * PADK * 4;
        sA[1] = base + 2 * 128 * PADK * 4;
        sB[1] = base + 3 * 128 * PADK * 4;
    }

    int nstage = K / 32;

    // prologue: stage 0 (each thread: 8 cp16 for A, 8 for B)
    {
        #pragma unroll
        for (int i = 0; i < 8; i++) {
            int e = t + i * 128;
            int row = e >> 3, c4 = (e & 7) * 4;
            cp16(sA[0] + (row * PADK + c4) * 4, A  + (size_t)(m0 + row) * K + c4);
            cp16(sB[0] + (row * PADK + c4) * 4, Wt + (size_t)(n0 + row) * K + c4);
        }
        asm volatile("cp.async.commit_group;\n");
    }

    for (int it = 0; it < nstage; it++) {
        asm volatile("cp.async.wait_group 0;\n");
        __syncthreads();
        int cur = it & 1;
        if (it + 1 < nstage) {
            int nxt = cur ^ 1;
            int k0 = (it + 1) * 32;
            #pragma unroll
            for (int i = 0; i < 8; i++) {
                int e = t + i * 128;
                int row = e >> 3, c4 = (e & 7) * 4;
                cp16(sA[nxt] + (row * PADK + c4) * 4,
                     A  + (size_t)(m0 + row) * K + k0 + c4);
                cp16(sB[nxt] + (row * PADK + c4) * 4,
                     Wt + (size_t)(n0 + row) * K + k0 + c4);
            }
            asm volatile("cp.async.commit_group;\n");
        }

        const float* Asc = As[cur];
        const float* Bsc = Bs[cur];
        #pragma unroll
        for (int kk = 0; kk < 32; kk += 8) {
            uint32_t a[4][4];
            #pragma unroll
            for (int mi = 0; mi < 4; mi++) {
                int r0 = wm * 64 + mi * 16 + g;
                a[mi][0] = __float_as_uint(Asc[(r0    ) * PADK + kk + tig    ]);
                a[mi][1] = __float_as_uint(Asc[(r0 + 8) * PADK + kk + tig    ]);
                a[mi][2] = __float_as_uint(Asc[(r0    ) * PADK + kk + tig + 4]);
                a[mi][3] = __float_as_uint(Asc[(r0 + 8) * PADK + kk + tig + 4]);
            }
            uint32_t b[8][2];
            #pragma unroll
            for (int nj = 0; nj < 8; nj++) {
                int c0 = wn * 64 + nj * 8 + g;
                b[nj][0] = __float_as_uint(Bsc[c0 * PADK + kk + tig    ]);
                b[nj][1] = __float_as_uint(Bsc[c0 * PADK + kk + tig + 4]);
            }
            #pragma unroll
            for (int mi = 0; mi < 4; mi++)
                #pragma unroll
                for (int nj = 0; nj < 8; nj++) {
                    asm volatile(
                        "mma.sync.aligned.m16n8k8.row.col.f32.tf32.tf32.f32 "
                        "{%0,%1,%2,%3}, {%4,%5,%6,%7}, {%8,%9}, {%0,%1,%2,%3};\n"
                        : "+f"(acc[mi][nj][0]), "+f"(acc[mi][nj][1]),
                          "+f"(acc[mi][nj][2]), "+f"(acc[mi][nj][3])
                        : "r"(a[mi][0]), "r"(a[mi][1]), "r"(a[mi][2]), "r"(a[mi][3]),
                          "r"(b[nj][0]), "r"(b[nj][1]));
                }
        }
        __syncthreads();
    }

    // epilogue
    #pragma unroll
    for (int mi = 0; mi < 4; mi++) {
        int r0 = m0 + wm * 64 + mi * 16 + g;
        #pragma unroll
        for (int nj = 0; nj < 8; nj++) {
            int c = n0 + wn * 64 + nj * 8 + tig * 2;
            float b0 = bias[c], b1 = bias[c + 1];
            #pragma unroll
            for (int half = 0; half < 2; half++) {
                int rr = r0 + half * 8;
                float v0 = acc[mi][nj][half * 2 + 0] + b0;
                float v1 = acc[mi][nj][half * 2 + 1] + b1;
                if (act_gelu) {
                    v0 = 0.5f * v0 * (1.0f + erff(v0 * 0.70710678118654752f));
                    v1 = 0.5f * v1 * (1.0f + erff(v1 * 0.70710678118654752f));
                }
                if (res) {
                    v0 += res[(size_t)rr * N + c];
                    v1 += res[(size_t)rr * N + c + 1];
                }
                if (round_out) { v0 = to_tf32(v0); v1 = to_tf32(v1); }
                *(float2*)(Cout + (size_t)rr * N + c) = make_float2(v0, v1);
            }
        }
    }
}

// ---------------------------------------------------------------------------
// Windowed attention + LePE; fp32 in, tf32-rounded fp32 out
// ---------------------------------------------------------------------------
__global__ __launch_bounds__(256) void attn_kernel(
    const float* __restrict__ qkv,
    const float* __restrict__ lw0, const float* __restrict__ lb0,
    const float* __restrict__ lw1, const float* __restrict__ lb1,
    float* __restrict__ out)
{
    extern __shared__ float smem[];
    float* Qs = smem;             // [256][32]
    float* Ks = smem + 8192;
    float* Vs = smem + 16384;
    __shared__ float wsh[32 * 9];
    __shared__ float bsh[32];

    int branch = blockIdx.y;
    int wh  = blockIdx.x;
    int win = wh / NHB;
    int hh  = wh % NHB;
    int batch = win / WIN_PER_B;
    int wloc  = win % WIN_PER_B;
    int t = threadIdx.x;

    const float* wptr = branch ? lw1 : lw0;
    const float* bptr = branch ? lb1 : lb0;
    for (int e = t; e < 288; e += 256) wsh[e] = wptr[hh * 288 + e];
    if (t < 32) bsh[t] = bptr[hh * 32 + t];

    int cbase = branch * CB + hh * HD;

    #pragma unroll 4
    for (int e = t; e < NWIN * HD; e += 256) {
        int n = e >> 5, d = e & 31;
        int l;
        if (branch == 0) l = (n >> 2) * 64 + wloc * 4 + (n & 3);
        else             l = (wloc * 4 + (n >> 6)) * 64 + (n & 63);
        size_t rowoff = ((size_t)batch * LTOK + l) * (3 * CDIM) + cbase + d;
        Qs[e] = qkv[rowoff];
        Ks[e] = qkv[rowoff + CDIM];
        Vs[e] = qkv[rowoff + 2 * CDIM];
    }
    __syncthreads();

    const float scale = 0.17677669529663687f;   // 1/sqrt(32)
    int n = t;
    float q[HD];
    #pragma unroll
    for (int d = 0; d < HD; d++) q[d] = Qs[n * HD + d] * scale;

    float m = -1e30f, lsum = 0.0f;
    float acc[HD];
    #pragma unroll
    for (int d = 0; d < HD; d++) acc[d] = 0.0f;

    for (int j = 0; j < NWIN; j++) {
        const float* kj = Ks + j * HD;
        float s = 0.0f;
        #pragma unroll
        for (int d = 0; d < HD; d++) s += q[d] * kj[d];
        const float* vj = Vs + j * HD;
        if (s <= m) {
            float p = __expf(s - m);
            lsum += p;
            #pragma unroll
            for (int d = 0; d < HD; d++) acc[d] += p * vj[d];
        } else {
            float f = __expf(m - s);
            lsum = lsum * f + 1.0f;
            #pragma unroll
            for (int d = 0; d < HD; d++) acc[d] = acc[d] * f + vj[d];
            m = s;
        }
    }
    float inv = 1.0f / lsum;

    int Hh = branch ? 4 : 64;
    int Wd = branch ? 64 : 4;
    int r  = n / Wd;
    int cc = n % Wd;
    int l;
    if (branch == 0) l = (n >> 2) * 64 + wloc * 4 + (n & 3);
    else             l = (wloc * 4 + (n >> 6)) * 64 + (n & 63);
    float* orow = out + ((size_t)batch * LTOK + l) * CDIM + cbase;

    #pragma unroll
    for (int d = 0; d < HD; d++) {
        float lep = bsh[d];
        #pragma unroll
        for (int dr = -1; dr <= 1; dr++) {
            int rr = r + dr;
            if (rr < 0 || rr >= Hh) continue;
            #pragma unroll
            for (int dc = -1; dc <= 1; dc++) {
                int c2 = cc + dc;
                if (c2 < 0 || c2 >= Wd) continue;
                lep += Vs[(rr * Wd + c2) * HD + d] * wsh[d * 9 + (dr + 1) * 3 + (dc + 1)];
            }
        }
        orow[d] = to_tf32(acc[d] * inv + lep);
    }
}

// ---------------------------------------------------------------------------
// Launch
// ---------------------------------------------------------------------------
#define GEMM_SMEM (4 * 128 * PADK * 4)   // 73728 bytes

extern "C" void kernel_launch(void* const* d_in, const int* in_sizes, int n_in,
                              void* d_out, int out_size)
{
    const float* x      = (const float*)d_in[0];
    const float* ln1_w  = (const float*)d_in[1];
    const float* ln1_b  = (const float*)d_in[2];
    const float* qkv_w  = (const float*)d_in[3];
    const float* qkv_b  = (const float*)d_in[4];
    const float* lw0    = (const float*)d_in[5];
    const float* lb0    = (const float*)d_in[6];
    const float* lw1    = (const float*)d_in[7];
    const float* lb1    = (const float*)d_in[8];
    const float* proj_w = (const float*)d_in[9];
    const float* proj_b = (const float*)d_in[10];
    const float* ln2_w  = (const float*)d_in[11];
    const float* ln2_b  = (const float*)d_in[12];
    const float* fc1_w  = (const float*)d_in[13];
    const float* fc1_b  = (const float*)d_in[14];
    const float* fc2_w  = (const float*)d_in[15];
    const float* fc2_b  = (const float*)d_in[16];
    float* out = (float*)d_out;

    float *p_ln, *p_qkv, *p_attn, *p_x1, *p_mlp, *p_wq, *p_wp, *p_w1, *p_w2;
    cudaGetSymbolAddress((void**)&p_ln,   g_ln);
    cudaGetSymbolAddress((void**)&p_qkv,  g_qkv);
    cudaGetSymbolAddress((void**)&p_attn, g_attn);
    cudaGetSymbolAddress((void**)&p_x1,   g_x1);
    cudaGetSymbolAddress((void**)&p_mlp,  g_mlp);
    cudaGetSymbolAddress((void**)&p_wq,   g_wq);
    cudaGetSymbolAddress((void**)&p_wp,   g_wp);
    cudaGetSymbolAddress((void**)&p_w1,   g_w1);
    cudaGetSymbolAddress((void**)&p_w2,   g_w2);

    cudaFuncSetAttribute(attn_kernel,
                         cudaFuncAttributeMaxDynamicSharedMemorySize, 98304);
    cudaFuncSetAttribute(gemm_tc_kernel,
                         cudaFuncAttributeMaxDynamicSharedMemorySize, GEMM_SMEM);

    // 0) round weights to tf32
    round_tf32_kernel<<<(3*CDIM*CDIM + 255)/256, 256>>>(qkv_w,  p_wq, 3*CDIM*CDIM);
    round_tf32_kernel<<<(CDIM*CDIM   + 255)/256, 256>>>(proj_w, p_wp, CDIM*CDIM);
    round_tf32_kernel<<<(MLPH*CDIM   + 255)/256, 256>>>(fc1_w,  p_w1, MLPH*CDIM);
    round_tf32_kernel<<<(CDIM*MLPH   + 255)/256, 256>>>(fc2_w,  p_w2, CDIM*MLPH);

    // 1) LN1
    ln_kernel<<<ROWS, 128>>>(x, ln1_w, ln1_b, p_ln);

    // 2) QKV GEMM
    gemm_tc_kernel<<<dim3(3*CDIM/128, ROWS/128), 128, GEMM_SMEM>>>(
        p_ln, p_wq, qkv_b, nullptr, p_qkv, ROWS, 3*CDIM, CDIM, 0, 0);

    // 3) attention
    attn_kernel<<<dim3(NWINDOWS * NHB, 2), 256, 98304>>>(
        p_qkv, lw0, lb0, lw1, lb1, p_attn);

    // 4) proj GEMM + residual(x)
    gemm_tc_kernel<<<dim3(CDIM/128, ROWS/128), 128, GEMM_SMEM>>>(
        p_attn, p_wp, proj_b, x, p_x1, ROWS, CDIM, CDIM, 0, 0);

    // 5) LN2
    ln_kernel<<<ROWS, 128>>>(p_x1, ln2_w, ln2_b, p_ln);

    // 6) fc1 GEMM + exact GELU (tf32-rounded out)
    gemm_tc_kernel<<<dim3(MLPH/128, ROWS/128), 128, GEMM_SMEM>>>(
        p_ln, p_w1, fc1_b, nullptr, p_mlp, ROWS, MLPH, CDIM, 1, 1);

    // 7) fc2 GEMM + residual(x1) -> out
    gemm_tc_kernel<<<dim3(CDIM/128, ROWS/128), 128, GEMM_SMEM>>>(
        p_mlp, p_w2, fc2_b, p_x1, out, ROWS, CDIM, MLPH, 0, 0);
}

// round 7
// speedup vs baseline: 1.2050x; 1.2050x over previous
#include <cuda_runtime.h>
#include <cuda_fp16.h>
#include <math.h>
#include <stdint.h>

// ---------------------------------------------------------------------------
// Problem constants
// ---------------------------------------------------------------------------
#define BATCH   8
#define RESO    64
#define LTOK    (RESO * RESO)        // 4096
#define CDIM    384
#define MLPH    (4 * CDIM)           // 1536
#define ROWS    (BATCH * LTOK)       // 32768
#define CB      (CDIM / 2)           // 192
#define NHB     6                    // heads per branch
#define HD      32
#define NWIN    256
#define WIN_PER_B 16
#define NWINDOWS (BATCH * WIN_PER_B) // 128

// ---------------------------------------------------------------------------
// Scratch (device globals; no allocation allowed)
// ---------------------------------------------------------------------------
__device__ float  g_qkv [ROWS * 3 * CDIM];
__device__ float  g_x1  [ROWS * CDIM];
__device__ __half g_ln_h[ROWS * CDIM];
__device__ __half g_at_h[ROWS * CDIM];
__device__ __half g_ml_h[ROWS * MLPH];
__device__ __half g_wq_h[3 * CDIM * CDIM];
__device__ __half g_wp_h[CDIM * CDIM];
__device__ __half g_w1_h[MLPH * CDIM];
__device__ __half g_w2_h[CDIM * MLPH];

// ---------------------------------------------------------------------------
// fp32 -> fp16 weight conversion
// ---------------------------------------------------------------------------
__global__ void whalf_kernel(const float* __restrict__ w,
                             __half* __restrict__ o, int n)
{
    int i = blockIdx.x * 256 + threadIdx.x;
    if (i < n) o[i] = __float2half_rn(w[i]);
}

// ---------------------------------------------------------------------------
// LayerNorm -> fp16 output (always feeds a GEMM A operand)
// ---------------------------------------------------------------------------
__global__ __launch_bounds__(128) void ln_kernel(
    const float* __restrict__ x, const float* __restrict__ w,
    const float* __restrict__ b, __half* __restrict__ out)
{
    int row = blockIdx.x;
    const float* xr = x + (size_t)row * CDIM;
    int t = threadIdx.x;

    float v0 = xr[t], v1 = xr[t + 128], v2 = xr[t + 256];
    float s  = v0 + v1 + v2;
    float ss = v0 * v0 + v1 * v1 + v2 * v2;

    #pragma unroll
    for (int o = 16; o > 0; o >>= 1) {
        s  += __shfl_down_sync(0xffffffffu, s,  o);
        ss += __shfl_down_sync(0xffffffffu, ss, o);
    }
    __shared__ float sh_s[4], sh_ss[4], sh_mu, sh_rstd;
    int wid = t >> 5, lane = t & 31;
    if (lane == 0) { sh_s[wid] = s; sh_ss[wid] = ss; }
    __syncthreads();
    if (t == 0) {
        float S  = sh_s[0] + sh_s[1] + sh_s[2] + sh_s[3];
        float SS = sh_ss[0] + sh_ss[1] + sh_ss[2] + sh_ss[3];
        float mu = S * (1.0f / CDIM);
        float var = SS * (1.0f / CDIM) - mu * mu;
        sh_mu = mu; sh_rstd = rsqrtf(var + 1e-5f);
    }
    __syncthreads();
    float mu = sh_mu, r = sh_rstd;
    __half* orow = out + (size_t)row * CDIM;
    orow[t]       = __float2half_rn((v0 - mu) * r * w[t]       + b[t]);
    orow[t + 128] = __float2half_rn((v1 - mu) * r * w[t + 128] + b[t + 128]);
    orow[t + 256] = __float2half_rn((v2 - mu) * r * w[t + 256] + b[t + 256]);
}

// ---------------------------------------------------------------------------
// FP16 tensor-core GEMM: C[M,N] = A[M,K] @ W[N,K]^T + bias (+gelu) (+res)
// 128x128x32 block tile, 256 threads (8 warps, 4x2 M-x-N), 32x64 warp tile,
// mma.sync.m16n8k16.f16 with fp32 accumulation, cp.async double buffering.
// Row stride 40 halves (20 words): fragment LDS banks = (20g+tig)%32, all
// 32 distinct -> conflict-free.
// ---------------------------------------------------------------------------
#define PADH 40                         // halves per row (32 data + 8 pad)
#define TILEH (128 * PADH)              // halves per tile

__device__ __forceinline__ void cp16(uint32_t dst, const void* src) {
    asm volatile("cp.async.ca.shared.global [%0], [%1], 16;\n"
                 :: "r"(dst), "l"(src));
}

__global__ __launch_bounds__(256, 2) void gemm_fp16_kernel(
    const __half* __restrict__ A, const __half* __restrict__ Wt,
    const float* __restrict__ bias, const float* __restrict__ res,
    float* __restrict__ out_f, __half* __restrict__ out_h,
    int M, int N, int K, int act_gelu)
{
    __shared__ __half smem[4 * TILEH];  // As0, Bs0, As1, Bs1  (40960 B)
    __half* As[2] = { smem,             smem + 2 * TILEH };
    __half* Bs[2] = { smem + TILEH,     smem + 3 * TILEH };

    int n0 = blockIdx.x * 128;
    int m0 = blockIdx.y * 128;
    int t  = threadIdx.x;
    int w  = t >> 5;
    int lane = t & 31;
    int g   = lane >> 2;      // 0..7
    int tig = lane & 3;       // 0..3
    int wm  = w >> 1;         // 0..3 (M)
    int wn  = w & 1;          // 0..1 (N)

    float acc[2][8][4];
    #pragma unroll
    for (int i = 0; i < 2; i++)
        #pragma unroll
        for (int j = 0; j < 8; j++)
            #pragma unroll
            for (int r = 0; r < 4; r++) acc[i][j][r] = 0.0f;

    uint32_t sbase = (uint32_t)__cvta_generic_to_shared(smem);
    uint32_t sA[2] = { sbase,                 sbase + 2 * TILEH * 2 };
    uint32_t sB[2] = { sbase + TILEH * 2,     sbase + 3 * TILEH * 2 };

    int nstage = K / 32;

    // stage loader: 128 rows x 32 halves per tile = 512 16B-chunks; 2/thread
    auto stage = [&](int k0, int buf) {
        #pragma unroll
        for (int i = 0; i < 2; i++) {
            int e = t + i * 256;            // 0..511
            int row = e >> 2, ch = e & 3;   // chunk of 8 halves
            uint32_t doff = (uint32_t)(row * PADH + ch * 8) * 2;
            cp16(sA[buf] + doff, A  + (size_t)(m0 + row) * K + k0 + ch * 8);
            cp16(sB[buf] + doff, Wt + (size_t)(n0 + row) * K + k0 + ch * 8);
        }
        asm volatile("cp.async.commit_group;\n");
    };

    stage(0, 0);

    for (int it = 0; it < nstage; it++) {
        asm volatile("cp.async.wait_group 0;\n");
        __syncthreads();
        int cur = it & 1;
        if (it + 1 < nstage) stage((it + 1) * 32, cur ^ 1);

        const __half* Asc = As[cur];
        const __half* Bsc = Bs[cur];
        #pragma unroll
        for (int kk = 0; kk < 32; kk += 16) {
            // fragments: each reg = half2 (2 consecutive k)
            uint32_t a[2][4];
            #pragma unroll
            for (int mi = 0; mi < 2; mi++) {
                int r0 = wm * 32 + mi * 16 + g;
                const __half* p0 = Asc + r0 * PADH + kk + 2 * tig;
                const __half* p1 = Asc + (r0 + 8) * PADH + kk + 2 * tig;
                a[mi][0] = *(const uint32_t*)p0;
                a[mi][1] = *(const uint32_t*)p1;
                a[mi][2] = *(const uint32_t*)(p0 + 8);
                a[mi][3] = *(const uint32_t*)(p1 + 8);
            }
            uint32_t b[8][2];
            #pragma unroll
            for (int nj = 0; nj < 8; nj++) {
                int c0 = wn * 64 + nj * 8 + g;
                const __half* p = Bsc + c0 * PADH + kk + 2 * tig;
                b[nj][0] = *(const uint32_t*)p;
                b[nj][1] = *(const uint32_t*)(p + 8);
            }
            #pragma unroll
            for (int mi = 0; mi < 2; mi++)
                #pragma unroll
                for (int nj = 0; nj < 8; nj++) {
                    asm volatile(
                        "mma.sync.aligned.m16n8k16.row.col.f32.f16.f16.f32 "
                        "{%0,%1,%2,%3}, {%4,%5,%6,%7}, {%8,%9}, {%0,%1,%2,%3};\n"
                        : "+f"(acc[mi][nj][0]), "+f"(acc[mi][nj][1]),
                          "+f"(acc[mi][nj][2]), "+f"(acc[mi][nj][3])
                        : "r"(a[mi][0]), "r"(a[mi][1]), "r"(a[mi][2]), "r"(a[mi][3]),
                          "r"(b[nj][0]), "r"(b[nj][1]));
                }
        }
        __syncthreads();
    }

    // epilogue
    #pragma unroll
    for (int mi = 0; mi < 2; mi++) {
        int r0 = m0 + wm * 32 + mi * 16 + g;
        #pragma unroll
        for (int nj = 0; nj < 8; nj++) {
            int c = n0 + wn * 64 + nj * 8 + tig * 2;
            float b0 = bias[c], b1 = bias[c + 1];
            #pragma unroll
            for (int half_i = 0; half_i < 2; half_i++) {
                int rr = r0 + half_i * 8;
                float v0 = acc[mi][nj][half_i * 2 + 0] + b0;
                float v1 = acc[mi][nj][half_i * 2 + 1] + b1;
                if (act_gelu) {
                    v0 = 0.5f * v0 * (1.0f + erff(v0 * 0.70710678118654752f));
                    v1 = 0.5f * v1 * (1.0f + erff(v1 * 0.70710678118654752f));
                }
                if (res) {
                    v0 += res[(size_t)rr * N + c];
                    v1 += res[(size_t)rr * N + c + 1];
                }
                if (out_f) {
                    *(float2*)(out_f + (size_t)rr * N + c) = make_float2(v0, v1);
                } else {
                    __half2 hv;
                    hv.x = __float2half_rn(v0);
                    hv.y = __float2half_rn(v1);
                    *(__half2*)(out_h + (size_t)rr * N + c) = hv;
                }
            }
        }
    }
}

// ---------------------------------------------------------------------------
// Windowed attention + LePE; fp32 in, fp16 out (feeds proj GEMM)
// ---------------------------------------------------------------------------
__global__ __launch_bounds__(256) void attn_kernel(
    const float* __restrict__ qkv,
    const float* __restrict__ lw0, const float* __restrict__ lb0,
    const float* __restrict__ lw1, const float* __restrict__ lb1,
    __half* __restrict__ out)
{
    extern __shared__ float asmem[];
    float* Qs = asmem;             // [256][32]
    float* Ks = asmem + 8192;
    float* Vs = asmem + 16384;
    __shared__ float wsh[32 * 9];
    __shared__ float bsh[32];

    int branch = blockIdx.y;
    int wh  = blockIdx.x;
    int win = wh / NHB;
    int hh  = wh % NHB;
    int batch = win / WIN_PER_B;
    int wloc  = win % WIN_PER_B;
    int t = threadIdx.x;

    const float* wptr = branch ? lw1 : lw0;
    const float* bptr = branch ? lb1 : lb0;
    for (int e = t; e < 288; e += 256) wsh[e] = wptr[hh * 288 + e];
    if (t < 32) bsh[t] = bptr[hh * 32 + t];

    int cbase = branch * CB + hh * HD;

    #pragma unroll 4
    for (int e = t; e < NWIN * HD; e += 256) {
        int n = e >> 5, d = e & 31;
        int l;
        if (branch == 0) l = (n >> 2) * 64 + wloc * 4 + (n & 3);
        else             l = (wloc * 4 + (n >> 6)) * 64 + (n & 63);
        size_t rowoff = ((size_t)batch * LTOK + l) * (3 * CDIM) + cbase + d;
        Qs[e] = qkv[rowoff];
        Ks[e] = qkv[rowoff + CDIM];
        Vs[e] = qkv[rowoff + 2 * CDIM];
    }
    __syncthreads();

    const float scale = 0.17677669529663687f;   // 1/sqrt(32)
    int n = t;
    float q[HD];
    #pragma unroll
    for (int d = 0; d < HD; d++) q[d] = Qs[n * HD + d] * scale;

    float m = -1e30f, lsum = 0.0f;
    float acc[HD];
    #pragma unroll
    for (int d = 0; d < HD; d++) acc[d] = 0.0f;

    for (int j = 0; j < NWIN; j++) {
        const float* kj = Ks + j * HD;
        float s = 0.0f;
        #pragma unroll
        for (int d = 0; d < HD; d++) s += q[d] * kj[d];
        const float* vj = Vs + j * HD;
        if (s <= m) {
            float p = __expf(s - m);
            lsum += p;
            #pragma unroll
            for (int d = 0; d < HD; d++) acc[d] += p * vj[d];
        } else {
            float f = __expf(m - s);
            lsum = lsum * f + 1.0f;
            #pragma unroll
            for (int d = 0; d < HD; d++) acc[d] = acc[d] * f + vj[d];
            m = s;
        }
    }
    float inv = 1.0f / lsum;

    int Hh = branch ? 4 : 64;
    int Wd = branch ? 64 : 4;
    int r  = n / Wd;
    int cc = n % Wd;
    int l;
    if (branch == 0) l = (n >> 2) * 64 + wloc * 4 + (n & 3);
    else             l = (wloc * 4 + (n >> 6)) * 64 + (n & 63);
    __half* orow = out + ((size_t)batch * LTOK + l) * CDIM + cbase;

    #pragma unroll
    for (int d = 0; d < HD; d++) {
        float lep = bsh[d];
        #pragma unroll
        for (int dr = -1; dr <= 1; dr++) {
            int rr = r + dr;
            if (rr < 0 || rr >= Hh) continue;
            #pragma unroll
            for (int dc = -1; dc <= 1; dc++) {
                int c2 = cc + dc;
                if (c2 < 0 || c2 >= Wd) continue;
                lep += Vs[(rr * Wd + c2) * HD + d] * wsh[d * 9 + (dr + 1) * 3 + (dc + 1)];
            }
        }
        orow[d] = __float2half_rn(acc[d] * inv + lep);
    }
}

// ---------------------------------------------------------------------------
// Launch
// ---------------------------------------------------------------------------
extern "C" void kernel_launch(void* const* d_in, const int* in_sizes, int n_in,
                              void* d_out, int out_size)
{
    const float* x      = (const float*)d_in[0];
    const float* ln1_w  = (const float*)d_in[1];
    const float* ln1_b  = (const float*)d_in[2];
    const float* qkv_w  = (const float*)d_in[3];
    const float* qkv_b  = (const float*)d_in[4];
    const float* lw0    = (const float*)d_in[5];
    const float* lb0    = (const float*)d_in[6];
    const float* lw1    = (const float*)d_in[7];
    const float* lb1    = (const float*)d_in[8];
    const float* proj_w = (const float*)d_in[9];
    const float* proj_b = (const float*)d_in[10];
    const float* ln2_w  = (const float*)d_in[11];
    const float* ln2_b  = (const float*)d_in[12];
    const float* fc1_w  = (const float*)d_in[13];
    const float* fc1_b  = (const float*)d_in[14];
    const float* fc2_w  = (const float*)d_in[15];
    const float* fc2_b  = (const float*)d_in[16];
    float* out = (float*)d_out;

    float *p_qkv, *p_x1;
    __half *p_ln, *p_at, *p_ml, *p_wq, *p_wp, *p_w1, *p_w2;
    cudaGetSymbolAddress((void**)&p_qkv, g_qkv);
    cudaGetSymbolAddress((void**)&p_x1,  g_x1);
    cudaGetSymbolAddress((void**)&p_ln,  g_ln_h);
    cudaGetSymbolAddress((void**)&p_at,  g_at_h);
    cudaGetSymbolAddress((void**)&p_ml,  g_ml_h);
    cudaGetSymbolAddress((void**)&p_wq,  g_wq_h);
    cudaGetSymbolAddress((void**)&p_wp,  g_wp_h);
    cudaGetSymbolAddress((void**)&p_w1,  g_w1_h);
    cudaGetSymbolAddress((void**)&p_w2,  g_w2_h);

    cudaFuncSetAttribute(attn_kernel,
                         cudaFuncAttributeMaxDynamicSharedMemorySize, 98304);

    // 0) weights -> fp16
    whalf_kernel<<<(3*CDIM*CDIM + 255)/256, 256>>>(qkv_w,  p_wq, 3*CDIM*CDIM);
    whalf_kernel<<<(CDIM*CDIM   + 255)/256, 256>>>(proj_w, p_wp, CDIM*CDIM);
    whalf_kernel<<<(MLPH*CDIM   + 255)/256, 256>>>(fc1_w,  p_w1, MLPH*CDIM);
    whalf_kernel<<<(CDIM*MLPH   + 255)/256, 256>>>(fc2_w,  p_w2, CDIM*MLPH);

    // 1) LN1 -> fp16
    ln_kernel<<<ROWS, 128>>>(x, ln1_w, ln1_b, p_ln);

    // 2) QKV GEMM -> fp32
    gemm_fp16_kernel<<<dim3(3*CDIM/128, ROWS/128), 256>>>(
        p_ln, p_wq, qkv_b, nullptr, p_qkv, nullptr, ROWS, 3*CDIM, CDIM, 0);

    // 3) attention -> fp16
    attn_kernel<<<dim3(NWINDOWS * NHB, 2), 256, 98304>>>(
        p_qkv, lw0, lb0, lw1, lb1, p_at);

    // 4) proj GEMM + residual(x) -> fp32 x1
    gemm_fp16_kernel<<<dim3(CDIM/128, ROWS/128), 256>>>(
        p_at, p_wp, proj_b, x, p_x1, nullptr, ROWS, CDIM, CDIM, 0);

    // 5) LN2 -> fp16
    ln_kernel<<<ROWS, 128>>>(p_x1, ln2_w, ln2_b, p_ln);

    // 6) fc1 GEMM + exact GELU -> fp16
    gemm_fp16_kernel<<<dim3(MLPH/128, ROWS/128), 256>>>(
        p_ln, p_w1, fc1_b, nullptr, nullptr, p_ml, ROWS, MLPH, CDIM, 1);

    // 7) fc2 GEMM + residual(x1) -> out (fp32)
    gemm_fp16_kernel<<<dim3(CDIM/128, ROWS/128), 256>>>(
        p_ml, p_w2, fc2_b, p_x1, out, nullptr, ROWS, CDIM, MLPH, 0);
}

// round 8
// speedup vs baseline: 1.2725x; 1.0560x over previous
#include <cuda_runtime.h>
#include <cuda_fp16.h>
#include <math.h>
#include <stdint.h>

// ---------------------------------------------------------------------------
// Problem constants
// ---------------------------------------------------------------------------
#define BATCH   8
#define RESO    64
#define LTOK    (RESO * RESO)        // 4096
#define CDIM    384
#define MLPH    (4 * CDIM)           // 1536
#define ROWS    (BATCH * LTOK)       // 32768
#define CB      (CDIM / 2)           // 192
#define NHB     6                    // heads per branch
#define HD      32
#define NWIN    256
#define WIN_PER_B 16
#define NWINDOWS (BATCH * WIN_PER_B) // 128

// ---------------------------------------------------------------------------
// Scratch (device globals; no allocation allowed)
// ---------------------------------------------------------------------------
__device__ float  g_qkv [ROWS * 3 * CDIM];
__device__ float  g_x1  [ROWS * CDIM];
__device__ __half g_ln_h[ROWS * CDIM];
__device__ __half g_at_h[ROWS * CDIM];
__device__ __half g_ml_h[ROWS * MLPH];
__device__ __half g_wq_h[3 * CDIM * CDIM];
__device__ __half g_wp_h[CDIM * CDIM];
__device__ __half g_w1_h[MLPH * CDIM];
__device__ __half g_w2_h[CDIM * MLPH];

// ---------------------------------------------------------------------------
// fp32 -> fp16 weight conversion
// ---------------------------------------------------------------------------
__global__ void whalf_kernel(const float* __restrict__ w,
                             __half* __restrict__ o, int n)
{
    int i = blockIdx.x * 256 + threadIdx.x;
    if (i < n) o[i] = __float2half_rn(w[i]);
}

// ---------------------------------------------------------------------------
// LayerNorm -> fp16 output
// ---------------------------------------------------------------------------
__global__ __launch_bounds__(128) void ln_kernel(
    const float* __restrict__ x, const float* __restrict__ w,
    const float* __restrict__ b, __half* __restrict__ out)
{
    int row = blockIdx.x;
    const float* xr = x + (size_t)row * CDIM;
    int t = threadIdx.x;

    float v0 = xr[t], v1 = xr[t + 128], v2 = xr[t + 256];
    float s  = v0 + v1 + v2;
    float ss = v0 * v0 + v1 * v1 + v2 * v2;

    #pragma unroll
    for (int o = 16; o > 0; o >>= 1) {
        s  += __shfl_down_sync(0xffffffffu, s,  o);
        ss += __shfl_down_sync(0xffffffffu, ss, o);
    }
    __shared__ float sh_s[4], sh_ss[4], sh_mu, sh_rstd;
    int wid = t >> 5, lane = t & 31;
    if (lane == 0) { sh_s[wid] = s; sh_ss[wid] = ss; }
    __syncthreads();
    if (t == 0) {
        float S  = sh_s[0] + sh_s[1] + sh_s[2] + sh_s[3];
        float SS = sh_ss[0] + sh_ss[1] + sh_ss[2] + sh_ss[3];
        float mu = S * (1.0f / CDIM);
        float var = SS * (1.0f / CDIM) - mu * mu;
        sh_mu = mu; sh_rstd = rsqrtf(var + 1e-5f);
    }
    __syncthreads();
    float mu = sh_mu, r = sh_rstd;
    __half* orow = out + (size_t)row * CDIM;
    orow[t]       = __float2half_rn((v0 - mu) * r * w[t]       + b[t]);
    orow[t + 128] = __float2half_rn((v1 - mu) * r * w[t + 128] + b[t + 128]);
    orow[t + 256] = __float2half_rn((v2 - mu) * r * w[t + 256] + b[t + 256]);
}

// ---------------------------------------------------------------------------
// FP16 tensor-core GEMM, 3-stage cp.async pipeline.
// 128x128x32 block tile, 256 threads (8 warps 4x2), 32x64 warp tile,
// mma.sync.m16n8k16.f32.f16.f16.f32. One __syncthreads per K-iteration;
// wait_group 1 gives each load ~2 iterations to land.
// ---------------------------------------------------------------------------
#define PADH 40                         // halves per row (32 data + 8 pad)
#define TILEH (128 * PADH)              // 5120 halves = 10240 B per tile
#define STAGEB (2 * TILEH * 2)          // A + B tile bytes = 20480
#define GSMEM  (3 * STAGEB)             // 61440 B

__device__ __forceinline__ void cp16(uint32_t dst, const void* src) {
    asm volatile("cp.async.ca.shared.global [%0], [%1], 16;\n"
                 :: "r"(dst), "l"(src));
}

__global__ __launch_bounds__(256, 2) void gemm_fp16_kernel(
    const __half* __restrict__ A, const __half* __restrict__ Wt,
    const float* __restrict__ bias, const float* __restrict__ res,
    float* __restrict__ out_f, __half* __restrict__ out_h,
    int M, int N, int K, int act_gelu)
{
    extern __shared__ __half smem[];

    int n0 = blockIdx.x * 128;
    int m0 = blockIdx.y * 128;
    int t  = threadIdx.x;
    int w  = t >> 5;
    int lane = t & 31;
    int g   = lane >> 2;      // 0..7
    int tig = lane & 3;       // 0..3
    int wm  = w >> 1;         // 0..3 (M)
    int wn  = w & 1;          // 0..1 (N)

    float acc[2][8][4];
    #pragma unroll
    for (int i = 0; i < 2; i++)
        #pragma unroll
        for (int j = 0; j < 8; j++)
            #pragma unroll
            for (int r = 0; r < 4; r++) acc[i][j][r] = 0.0f;

    uint32_t sbase = (uint32_t)__cvta_generic_to_shared(smem);

    int nch = K / 32;

    // stage a K-chunk into ring slot s
    auto stage = [&](int k0, int s) {
        uint32_t sA = sbase + (uint32_t)s * STAGEB;
        uint32_t sB = sA + TILEH * 2;
        #pragma unroll
        for (int i = 0; i < 2; i++) {
            int e = t + i * 256;            // 0..511
            int row = e >> 2, ch = e & 3;   // 16B chunk (8 halves)
            uint32_t doff = (uint32_t)(row * PADH + ch * 8) * 2;
            cp16(sA + doff, A  + (size_t)(m0 + row) * K + k0 + ch * 8);
            cp16(sB + doff, Wt + (size_t)(n0 + row) * K + k0 + ch * 8);
        }
        asm volatile("cp.async.commit_group;\n");
    };

    stage(0, 0);
    stage(32, 1);

    for (int it = 0; it < nch; it++) {
        int s = it % 3;
        if (it == nch - 1)
            asm volatile("cp.async.wait_group 0;\n");
        else
            asm volatile("cp.async.wait_group 1;\n");
        __syncthreads();

        // prefetch it+2 into the slot consumed at iteration it-1
        if (it + 2 < nch) stage((it + 2) * 32, (it + 2) % 3);

        const __half* Asc = smem + (size_t)s * (STAGEB / 2);
        const __half* Bsc = Asc + TILEH;
        #pragma unroll
        for (int kk = 0; kk < 32; kk += 16) {
            uint32_t a[2][4];
            #pragma unroll
            for (int mi = 0; mi < 2; mi++) {
                int r0 = wm * 32 + mi * 16 + g;
                const __half* p0 = Asc + r0 * PADH + kk + 2 * tig;
                const __half* p1 = Asc + (r0 + 8) * PADH + kk + 2 * tig;
                a[mi][0] = *(const uint32_t*)p0;
                a[mi][1] = *(const uint32_t*)p1;
                a[mi][2] = *(const uint32_t*)(p0 + 8);
                a[mi][3] = *(const uint32_t*)(p1 + 8);
            }
            uint32_t b[8][2];
            #pragma unroll
            for (int nj = 0; nj < 8; nj++) {
                int c0 = wn * 64 + nj * 8 + g;
                const __half* p = Bsc + c0 * PADH + kk + 2 * tig;
                b[nj][0] = *(const uint32_t*)p;
                b[nj][1] = *(const uint32_t*)(p + 8);
            }
            #pragma unroll
            for (int mi = 0; mi < 2; mi++)
                #pragma unroll
                for (int nj = 0; nj < 8; nj++) {
                    asm volatile(
                        "mma.sync.aligned.m16n8k16.row.col.f32.f16.f16.f32 "
                        "{%0,%1,%2,%3}, {%4,%5,%6,%7}, {%8,%9}, {%0,%1,%2,%3};\n"
                        : "+f"(acc[mi][nj][0]), "+f"(acc[mi][nj][1]),
                          "+f"(acc[mi][nj][2]), "+f"(acc[mi][nj][3])
                        : "r"(a[mi][0]), "r"(a[mi][1]), "r"(a[mi][2]), "r"(a[mi][3]),
                          "r"(b[nj][0]), "r"(b[nj][1]));
                }
        }
        __syncthreads();
    }

    // epilogue
    #pragma unroll
    for (int mi = 0; mi < 2; mi++) {
        int r0 = m0 + wm * 32 + mi * 16 + g;
        #pragma unroll
        for (int nj = 0; nj < 8; nj++) {
            int c = n0 + wn * 64 + nj * 8 + tig * 2;
            float b0 = bias[c], b1 = bias[c + 1];
            #pragma unroll
            for (int half_i = 0; half_i < 2; half_i++) {
                int rr = r0 + half_i * 8;
                float v0 = acc[mi][nj][half_i * 2 + 0] + b0;
                float v1 = acc[mi][nj][half_i * 2 + 1] + b1;
                if (act_gelu) {
                    v0 = 0.5f * v0 * (1.0f + erff(v0 * 0.70710678118654752f));
                    v1 = 0.5f * v1 * (1.0f + erff(v1 * 0.70710678118654752f));
                }
                if (res) {
                    v0 += res[(size_t)rr * N + c];
                    v1 += res[(size_t)rr * N + c + 1];
                }
                if (out_f) {
                    *(float2*)(out_f + (size_t)rr * N + c) = make_float2(v0, v1);
                } else {
                    __half2 hv;
                    hv.x = __float2half_rn(v0);
                    hv.y = __float2half_rn(v1);
                    *(__half2*)(out_h + (size_t)rr * N + c) = hv;
                }
            }
        }
    }
}

// ---------------------------------------------------------------------------
// Windowed attention + LePE; fp32 in, fp16 out
// ---------------------------------------------------------------------------
__global__ __launch_bounds__(256) void attn_kernel(
    const float* __restrict__ qkv,
    const float* __restrict__ lw0, const float* __restrict__ lb0,
    const float* __restrict__ lw1, const float* __restrict__ lb1,
    __half* __restrict__ out)
{
    extern __shared__ float asmem[];
    float* Qs = asmem;             // [256][32]
    float* Ks = asmem + 8192;
    float* Vs = asmem + 16384;
    __shared__ float wsh[32 * 9];
    __shared__ float bsh[32];

    int branch = blockIdx.y;
    int wh  = blockIdx.x;
    int win = wh / NHB;
    int hh  = wh % NHB;
    int batch = win / WIN_PER_B;
    int wloc  = win % WIN_PER_B;
    int t = threadIdx.x;

    const float* wptr = branch ? lw1 : lw0;
    const float* bptr = branch ? lb1 : lb0;
    for (int e = t; e < 288; e += 256) wsh[e] = wptr[hh * 288 + e];
    if (t < 32) bsh[t] = bptr[hh * 32 + t];

    int cbase = branch * CB + hh * HD;

    #pragma unroll 4
    for (int e = t; e < NWIN * HD; e += 256) {
        int n = e >> 5, d = e & 31;
        int l;
        if (branch == 0) l = (n >> 2) * 64 + wloc * 4 + (n & 3);
        else             l = (wloc * 4 + (n >> 6)) * 64 + (n & 63);
        size_t rowoff = ((size_t)batch * LTOK + l) * (3 * CDIM) + cbase + d;
        Qs[e] = qkv[rowoff];
        Ks[e] = qkv[rowoff + CDIM];
        Vs[e] = qkv[rowoff + 2 * CDIM];
    }
    __syncthreads();

    const float scale = 0.17677669529663687f;   // 1/sqrt(32)
    int n = t;
    float q[HD];
    #pragma unroll
    for (int d = 0; d < HD; d++) q[d] = Qs[n * HD + d] * scale;

    float m = -1e30f, lsum = 0.0f;
    float acc[HD];
    #pragma unroll
    for (int d = 0; d < HD; d++) acc[d] = 0.0f;

    for (int j = 0; j < NWIN; j++) {
        const float* kj = Ks + j * HD;
        float s = 0.0f;
        #pragma unroll
        for (int d = 0; d < HD; d++) s += q[d] * kj[d];
        const float* vj = Vs + j * HD;
        if (s <= m) {
            float p = __expf(s - m);
            lsum += p;
            #pragma unroll
            for (int d = 0; d < HD; d++) acc[d] += p * vj[d];
        } else {
            float f = __expf(m - s);
            lsum = lsum * f + 1.0f;
            #pragma unroll
            for (int d = 0; d < HD; d++) acc[d] = acc[d] * f + vj[d];
            m = s;
        }
    }
    float inv = 1.0f / lsum;

    int Hh = branch ? 4 : 64;
    int Wd = branch ? 64 : 4;
    int r  = n / Wd;
    int cc = n % Wd;
    int l;
    if (branch == 0) l = (n >> 2) * 64 + wloc * 4 + (n & 3);
    else             l = (wloc * 4 + (n >> 6)) * 64 + (n & 63);
    __half* orow = out + ((size_t)batch * LTOK + l) * CDIM + cbase;

    #pragma unroll
    for (int d = 0; d < HD; d++) {
        float lep = bsh[d];
        #pragma unroll
        for (int dr = -1; dr <= 1; dr++) {
            int rr = r + dr;
            if (rr < 0 || rr >= Hh) continue;
            #pragma unroll
            for (int dc = -1; dc <= 1; dc++) {
                int c2 = cc + dc;
                if (c2 < 0 || c2 >= Wd) continue;
                lep += Vs[(rr * Wd + c2) * HD + d] * wsh[d * 9 + (dr + 1) * 3 + (dc + 1)];
            }
        }
        orow[d] = __float2half_rn(acc[d] * inv + lep);
    }
}

// ---------------------------------------------------------------------------
// Launch
// ---------------------------------------------------------------------------
extern "C" void kernel_launch(void* const* d_in, const int* in_sizes, int n_in,
                              void* d_out, int out_size)
{
    const float* x      = (const float*)d_in[0];
    const float* ln1_w  = (const float*)d_in[1];
    const float* ln1_b  = (const float*)d_in[2];
    const float* qkv_w  = (const float*)d_in[3];
    const float* qkv_b  = (const float*)d_in[4];
    const float* lw0    = (const float*)d_in[5];
    const float* lb0    = (const float*)d_in[6];
    const float* lw1    = (const float*)d_in[7];
    const float* lb1    = (const float*)d_in[8];
    const float* proj_w = (const float*)d_in[9];
    const float* proj_b = (const float*)d_in[10];
    const float* ln2_w  = (const float*)d_in[11];
    const float* ln2_b  = (const float*)d_in[12];
    const float* fc1_w  = (const float*)d_in[13];
    const float* fc1_b  = (const float*)d_in[14];
    const float* fc2_w  = (const float*)d_in[15];
    const float* fc2_b  = (const float*)d_in[16];
    float* out = (float*)d_out;

    float *p_qkv, *p_x1;
    __half *p_ln, *p_at, *p_ml, *p_wq, *p_wp, *p_w1, *p_w2;
    cudaGetSymbolAddress((void**)&p_qkv, g_qkv);
    cudaGetSymbolAddress((void**)&p_x1,  g_x1);
    cudaGetSymbolAddress((void**)&p_ln,  g_ln_h);
    cudaGetSymbolAddress((void**)&p_at,  g_at_h);
    cudaGetSymbolAddress((void**)&p_ml,  g_ml_h);
    cudaGetSymbolAddress((void**)&p_wq,  g_wq_h);
    cudaGetSymbolAddress((void**)&p_wp,  g_wp_h);
    cudaGetSymbolAddress((void**)&p_w1,  g_w1_h);
    cudaGetSymbolAddress((void**)&p_w2,  g_w2_h);

    cudaFuncSetAttribute(attn_kernel,
                         cudaFuncAttributeMaxDynamicSharedMemorySize, 98304);
    cudaFuncSetAttribute(gemm_fp16_kernel,
                         cudaFuncAttributeMaxDynamicSharedMemorySize, GSMEM);

    // 0) weights -> fp16
    whalf_kernel<<<(3*CDIM*CDIM + 255)/256, 256>>>(qkv_w,  p_wq, 3*CDIM*CDIM);
    whalf_kernel<<<(CDIM*CDIM   + 255)/256, 256>>>(proj_w, p_wp, CDIM*CDIM);
    whalf_kernel<<<(MLPH*CDIM   + 255)/256, 256>>>(fc1_w,  p_w1, MLPH*CDIM);
    whalf_kernel<<<(CDIM*MLPH   + 255)/256, 256>>>(fc2_w,  p_w2, CDIM*MLPH);

    // 1) LN1 -> fp16
    ln_kernel<<<ROWS, 128>>>(x, ln1_w, ln1_b, p_ln);

    // 2) QKV GEMM -> fp32
    gemm_fp16_kernel<<<dim3(3*CDIM/128, ROWS/128), 256, GSMEM>>>(
        p_ln, p_wq, qkv_b, nullptr, p_qkv, nullptr, ROWS, 3*CDIM, CDIM, 0);

    // 3) attention -> fp16
    attn_kernel<<<dim3(NWINDOWS * NHB, 2), 256, 98304>>>(
        p_qkv, lw0, lb0, lw1, lb1, p_at);

    // 4) proj GEMM + residual(x) -> fp32 x1
    gemm_fp16_kernel<<<dim3(CDIM/128, ROWS/128), 256, GSMEM>>>(
        p_at, p_wp, proj_b, x, p_x1, nullptr, ROWS, CDIM, CDIM, 0);

    // 5) LN2 -> fp16
    ln_kernel<<<ROWS, 128>>>(p_x1, ln2_w, ln2_b, p_ln);

    // 6) fc1 GEMM + exact GELU -> fp16
    gemm_fp16_kernel<<<dim3(MLPH/128, ROWS/128), 256, GSMEM>>>(
        p_ln, p_w1, fc1_b, nullptr, nullptr, p_ml, ROWS, MLPH, CDIM, 1);

    // 7) fc2 GEMM + residual(x1) -> out (fp32)
    gemm_fp16_kernel<<<dim3(CDIM/128, ROWS/128), 256, GSMEM>>>(
        p_ml, p_w2, fc2_b, p_x1, out, nullptr, ROWS, CDIM, MLPH, 0);
}